// round 8
// baseline (speedup 1.0000x reference)
#include <cuda_runtime.h>
#include <cuda_fp16.h>
#include <cstdint>

// ============================================================================
// MambaBlock, fp16 asymmetric 2-product HMMA (A = hi+lo fp16, B = fp16 round).
// R8: conversions fused into GEMM loaders (no standalone cvt kernels).
//   GEMM1: x,Wi fp32 -> (split,round) in loader.  GEMM2: Wo fp32 -> round.
// ============================================================================

#define MROWS 16384
#define DDIM  1024
#define LSEQ  4096

#define BM 128
#define BN 128
#define BK 32
#define SP 40                    // SMEM row stride in fp16 (32 + 8 pad)
#define NTH 256

#define A_HI 0
#define A_LO (BM * SP * 2)       // 10240
#define B_OF (2 * BM * SP * 2)   // 20480
#define STAGE_BYTES (3 * BM * SP * 2)   // 30720
#define SMEMSZ (2 * STAGE_BYTES)        // 61440

__device__ float g_uv[(size_t)MROWS * 2 * DDIM];
__device__ __half g_yhi[(size_t)MROWS * DDIM];
__device__ __half g_ylo[(size_t)MROWS * DDIM];

__device__ __forceinline__ void mma_f16(float* c, const uint32_t* a,
                                        uint32_t b0, uint32_t b1) {
    asm volatile(
        "mma.sync.aligned.m16n8k16.row.col.f32.f16.f16.f32 "
        "{%0,%1,%2,%3}, {%4,%5,%6,%7}, {%8,%9}, {%0,%1,%2,%3};"
        : "+f"(c[0]), "+f"(c[1]), "+f"(c[2]), "+f"(c[3])
        : "r"(a[0]), "r"(a[1]), "r"(a[2]), "r"(a[3]), "r"(b0), "r"(b1));
}

#define LDSM4(r0, r1, r2, r3, addr)                                        \
    asm volatile("ldmatrix.sync.aligned.m8n8.x4.shared.b16 {%0,%1,%2,%3}, [%4];" \
                 : "=r"(r0), "=r"(r1), "=r"(r2), "=r"(r3) : "r"(addr))

#define STS128(addr, r0, r1, r2, r3)                                       \
    asm volatile("st.shared.v4.b32 [%0], {%1,%2,%3,%4};"                   \
                 :: "r"(addr), "r"(r0), "r"(r1), "r"(r2), "r"(r3))

#define CPA16(dst, src) \
    asm volatile("cp.async.cg.shared.global [%0], [%1], 16;" :: "r"(dst), "l"(src))
#define CP_COMMIT() asm volatile("cp.async.commit_group;" ::: "memory")
#define CP_WAIT1()  asm volatile("cp.async.wait_group 1;" ::: "memory")
#define CP_WAIT0()  asm volatile("cp.async.wait_group 0;" ::: "memory")

// 8 fp32 -> 4 words fp16 hi + 4 words fp16 lo
__device__ __forceinline__ void cvt8_split(float4 v0, float4 v1,
                                           uint32_t* h, uint32_t* l) {
    __half2 H0 = __floats2half2_rn(v0.x, v0.y);
    __half2 H1 = __floats2half2_rn(v0.z, v0.w);
    __half2 H2 = __floats2half2_rn(v1.x, v1.y);
    __half2 H3 = __floats2half2_rn(v1.z, v1.w);
    __half2 L0 = __floats2half2_rn(v0.x - __low2float(H0), v0.y - __high2float(H0));
    __half2 L1 = __floats2half2_rn(v0.z - __low2float(H1), v0.w - __high2float(H1));
    __half2 L2 = __floats2half2_rn(v1.x - __low2float(H2), v1.y - __high2float(H2));
    __half2 L3 = __floats2half2_rn(v1.z - __low2float(H3), v1.w - __high2float(H3));
    h[0] = *reinterpret_cast<uint32_t*>(&H0); h[1] = *reinterpret_cast<uint32_t*>(&H1);
    h[2] = *reinterpret_cast<uint32_t*>(&H2); h[3] = *reinterpret_cast<uint32_t*>(&H3);
    l[0] = *reinterpret_cast<uint32_t*>(&L0); l[1] = *reinterpret_cast<uint32_t*>(&L1);
    l[2] = *reinterpret_cast<uint32_t*>(&L2); l[3] = *reinterpret_cast<uint32_t*>(&L3);
}

// 8 fp32 -> 4 words fp16 (round)
__device__ __forceinline__ void cvt8_round(float4 v0, float4 v1, uint32_t* h) {
    __half2 H0 = __floats2half2_rn(v0.x, v0.y);
    __half2 H1 = __floats2half2_rn(v0.z, v0.w);
    __half2 H2 = __floats2half2_rn(v1.x, v1.y);
    __half2 H3 = __floats2half2_rn(v1.z, v1.w);
    h[0] = *reinterpret_cast<uint32_t*>(&H0); h[1] = *reinterpret_cast<uint32_t*>(&H1);
    h[2] = *reinterpret_cast<uint32_t*>(&H2); h[3] = *reinterpret_cast<uint32_t*>(&H3);
}

// ---------------------------------------------------------------------------
// GEMM1: C[M,N] = x[M,K] @ Wi[N,K]^T + bias; fp32 in, split/round in loader.
// ---------------------------------------------------------------------------
template <int N, int K>
__global__ __launch_bounds__(NTH)
void gemm1_fused(const float* __restrict__ A, const float* __restrict__ B,
                 const float* __restrict__ bias, float* __restrict__ C) {
    extern __shared__ __align__(16) char sm[];
    const uint32_t smb = (uint32_t)__cvta_generic_to_shared(sm);
    const int tid  = threadIdx.x;
    const int lane = tid & 31;
    const int wid  = tid >> 5;
    const int wm   = wid & 3;
    const int wn   = wid >> 2;
    const int qr   = lane >> 2;
    const int qc   = (lane & 3) * 2;
    const int row0 = blockIdx.y * BM;
    const int col0 = blockIdx.x * BN;

    const int m8 = lane >> 3;
    const int rr = lane & 7;
    const uint32_t aLane = (uint32_t)(((wm * 32 + (m8 & 1) * 8 + rr) * SP + (m8 >> 1) * 8) * 2);
    const uint32_t bLane = (uint32_t)(((wn * 64 + (m8 >> 1) * 8 + rr) * SP + (m8 & 1) * 8) * 2);

    const int lr = tid >> 2;         // rows 0..63, +64 per rep
    const int lq = tid & 3;          // 8-col group

    float acc[2][8][4];
#pragma unroll
    for (int i = 0; i < 2; i++)
#pragma unroll
        for (int j = 0; j < 8; j++)
#pragma unroll
            for (int k = 0; k < 4; k++) acc[i][j][k] = 0.f;

    const float* Ab = A + (size_t)row0 * K;
    const float* Bb = B + (size_t)col0 * K;

    float4 fa[2][2], fb[2][2];

#define FETCH1(kt) do {                                                        \
    _Pragma("unroll")                                                          \
    for (int rep = 0; rep < 2; rep++) {                                        \
        int r = lr + rep * 64;                                                 \
        const float* pa = Ab + (size_t)r * K + (kt) + lq * 8;                  \
        const float* pb = Bb + (size_t)r * K + (kt) + lq * 8;                  \
        fa[rep][0] = *(const float4*)pa;  fa[rep][1] = *(const float4*)(pa + 4); \
        fb[rep][0] = *(const float4*)pb;  fb[rep][1] = *(const float4*)(pb + 4); \
    }                                                                          \
} while (0)

#define STORE1(stageOff) do {                                                  \
    const uint32_t so_ = smb + (stageOff);                                     \
    _Pragma("unroll")                                                          \
    for (int rep = 0; rep < 2; rep++) {                                        \
        int r = lr + rep * 64;                                                 \
        uint32_t d = so_ + (uint32_t)((r * SP + lq * 8) * 2);                  \
        uint32_t h[4], l[4];                                                   \
        cvt8_split(fa[rep][0], fa[rep][1], h, l);                              \
        STS128(d + A_HI, h[0], h[1], h[2], h[3]);                              \
        STS128(d + A_LO, l[0], l[1], l[2], l[3]);                              \
        cvt8_round(fb[rep][0], fb[rep][1], h);                                 \
        STS128(d + B_OF, h[0], h[1], h[2], h[3]);                              \
    }                                                                          \
} while (0)

    // prologue: chunk 0 -> stage 0
    FETCH1(0);
    STORE1(0);

    constexpr int NCH = K / BK;
#pragma unroll 1
    for (int ck = 0; ck < NCH; ck++) {
        __syncthreads();
        const bool pf = (ck + 1 < NCH);
        if (pf) FETCH1((ck + 1) * BK);

        const uint32_t sto = smb + (uint32_t)((ck & 1) * STAGE_BYTES);
#pragma unroll
        for (int kb = 0; kb < BK; kb += 16) {
            uint32_t ah[2][4], al[2][4], bb[4][4];
#pragma unroll
            for (int mt = 0; mt < 2; mt++) {
                uint32_t ao = sto + aLane + (uint32_t)((mt * 16 * SP + kb) * 2);
                LDSM4(ah[mt][0], ah[mt][1], ah[mt][2], ah[mt][3], ao + A_HI);
                LDSM4(al[mt][0], al[mt][1], al[mt][2], al[mt][3], ao + A_LO);
            }
#pragma unroll
            for (int ntp = 0; ntp < 4; ntp++) {
                uint32_t bo = sto + bLane + (uint32_t)((ntp * 16 * SP + kb) * 2);
                LDSM4(bb[ntp][0], bb[ntp][1], bb[ntp][2], bb[ntp][3], bo + B_OF);
            }
#pragma unroll
            for (int mt = 0; mt < 2; mt++)
#pragma unroll
                for (int ntp = 0; ntp < 4; ntp++) {
                    mma_f16(acc[mt][2 * ntp],     ah[mt], bb[ntp][0], bb[ntp][1]);
                    mma_f16(acc[mt][2 * ntp + 1], ah[mt], bb[ntp][2], bb[ntp][3]);
                }
#pragma unroll
            for (int mt = 0; mt < 2; mt++)
#pragma unroll
                for (int ntp = 0; ntp < 4; ntp++) {
                    mma_f16(acc[mt][2 * ntp],     al[mt], bb[ntp][0], bb[ntp][1]);
                    mma_f16(acc[mt][2 * ntp + 1], al[mt], bb[ntp][2], bb[ntp][3]);
                }
        }
        if (pf) STORE1((uint32_t)(((ck + 1) & 1) * STAGE_BYTES));
    }
#undef FETCH1
#undef STORE1

#pragma unroll
    for (int mt = 0; mt < 2; mt++) {
        int row = row0 + wm * 32 + mt * 16 + qr;
#pragma unroll
        for (int nt = 0; nt < 8; nt++) {
            int col = col0 + wn * 64 + nt * 8 + qc;
            float b0 = __ldg(&bias[col]);
            float b1 = __ldg(&bias[col + 1]);
            float2 o0 = make_float2(acc[mt][nt][0] + b0, acc[mt][nt][1] + b1);
            float2 o1 = make_float2(acc[mt][nt][2] + b0, acc[mt][nt][3] + b1);
            *(float2*)(C + (size_t)row * N + col) = o0;
            *(float2*)(C + (size_t)(row + 8) * N + col) = o1;
        }
    }
}

// ---------------------------------------------------------------------------
// GEMM2: C[M,N] = (Yhi+Ylo)[M,K] @ Wo[N,K]^T + bias.
// A via cp.async (pre-split fp16), B rounded fp32->fp16 in loader.
// ---------------------------------------------------------------------------
template <int N, int K>
__global__ __launch_bounds__(NTH)
void gemm2_fused(const __half* __restrict__ Ahi, const __half* __restrict__ Alo,
                 const float* __restrict__ B,
                 const float* __restrict__ bias, float* __restrict__ C) {
    extern __shared__ __align__(16) char sm[];
    const uint32_t smb = (uint32_t)__cvta_generic_to_shared(sm);
    const int tid  = threadIdx.x;
    const int lane = tid & 31;
    const int wid  = tid >> 5;
    const int wm   = wid & 3;
    const int wn   = wid >> 2;
    const int qr   = lane >> 2;
    const int qc   = (lane & 3) * 2;
    const int row0 = blockIdx.y * BM;
    const int col0 = blockIdx.x * BN;

    const int m8 = lane >> 3;
    const int rr = lane & 7;
    const uint32_t aLane = (uint32_t)(((wm * 32 + (m8 & 1) * 8 + rr) * SP + (m8 >> 1) * 8) * 2);
    const uint32_t bLane = (uint32_t)(((wn * 64 + (m8 >> 1) * 8 + rr) * SP + (m8 & 1) * 8) * 2);

    const int lr  = tid >> 2;        // rows 0..63 (+64)
    const int lq  = tid & 3;
    const int l_c = lq * 16;         // byte col for cp.async

    float acc[2][8][4];
#pragma unroll
    for (int i = 0; i < 2; i++)
#pragma unroll
        for (int j = 0; j < 8; j++)
#pragma unroll
            for (int k = 0; k < 4; k++) acc[i][j][k] = 0.f;

    const char* pAh = (const char*)(Ahi + (size_t)row0 * K);
    const char* pAl = (const char*)(Alo + (size_t)row0 * K);
    const float* Bb = B + (size_t)col0 * K;

    float4 fb[2][2];

#define LOAD_A2(stageOff, kt) do {                                             \
    const uint32_t so_ = smb + (stageOff);                                     \
    const size_t kb_ = (size_t)(kt) * 2;                                       \
    _Pragma("unroll")                                                          \
    for (int rep = 0; rep < 2; rep++) {                                        \
        int r = lr + rep * 64;                                                 \
        uint32_t d = so_ + (uint32_t)(r * (SP * 2) + l_c);                     \
        size_t g = (size_t)r * (K * 2) + kb_ + l_c;                            \
        CPA16(d + A_HI, pAh + g);                                              \
        CPA16(d + A_LO, pAl + g);                                              \
    }                                                                          \
} while (0)

#define FETCH_B2(kt) do {                                                      \
    _Pragma("unroll")                                                          \
    for (int rep = 0; rep < 2; rep++) {                                        \
        int r = lr + rep * 64;                                                 \
        const float* pb = Bb + (size_t)r * K + (kt) + lq * 8;                  \
        fb[rep][0] = *(const float4*)pb;  fb[rep][1] = *(const float4*)(pb + 4); \
    }                                                                          \
} while (0)

#define STORE_B2(stageOff) do {                                                \
    const uint32_t so_ = smb + (stageOff);                                     \
    _Pragma("unroll")                                                          \
    for (int rep = 0; rep < 2; rep++) {                                        \
        int r = lr + rep * 64;                                                 \
        uint32_t d = so_ + (uint32_t)((r * SP + lq * 8) * 2);                  \
        uint32_t h[4];                                                         \
        cvt8_round(fb[rep][0], fb[rep][1], h);                                 \
        STS128(d + B_OF, h[0], h[1], h[2], h[3]);                              \
    }                                                                          \
} while (0)

    // prologue: chunk 0 -> stage 0
    LOAD_A2(0, 0);
    CP_COMMIT();
    FETCH_B2(0);
    STORE_B2(0);

    constexpr int NCH = K / BK;
#pragma unroll 1
    for (int ck = 0; ck < NCH; ck++) {
        const bool pf = (ck + 1 < NCH);
        if (pf) {
            LOAD_A2((uint32_t)(((ck + 1) & 1) * STAGE_BYTES), (ck + 1) * BK);
            CP_COMMIT();
            CP_WAIT1();
        } else {
            CP_WAIT0();
        }
        __syncthreads();
        if (pf) FETCH_B2((ck + 1) * BK);

        const uint32_t sto = smb + (uint32_t)((ck & 1) * STAGE_BYTES);
#pragma unroll
        for (int kb = 0; kb < BK; kb += 16) {
            uint32_t ah[2][4], al[2][4], bb[4][4];
#pragma unroll
            for (int mt = 0; mt < 2; mt++) {
                uint32_t ao = sto + aLane + (uint32_t)((mt * 16 * SP + kb) * 2);
                LDSM4(ah[mt][0], ah[mt][1], ah[mt][2], ah[mt][3], ao + A_HI);
                LDSM4(al[mt][0], al[mt][1], al[mt][2], al[mt][3], ao + A_LO);
            }
#pragma unroll
            for (int ntp = 0; ntp < 4; ntp++) {
                uint32_t bo = sto + bLane + (uint32_t)((ntp * 16 * SP + kb) * 2);
                LDSM4(bb[ntp][0], bb[ntp][1], bb[ntp][2], bb[ntp][3], bo + B_OF);
            }
#pragma unroll
            for (int mt = 0; mt < 2; mt++)
#pragma unroll
                for (int ntp = 0; ntp < 4; ntp++) {
                    mma_f16(acc[mt][2 * ntp],     ah[mt], bb[ntp][0], bb[ntp][1]);
                    mma_f16(acc[mt][2 * ntp + 1], ah[mt], bb[ntp][2], bb[ntp][3]);
                }
#pragma unroll
            for (int mt = 0; mt < 2; mt++)
#pragma unroll
                for (int ntp = 0; ntp < 4; ntp++) {
                    mma_f16(acc[mt][2 * ntp],     al[mt], bb[ntp][0], bb[ntp][1]);
                    mma_f16(acc[mt][2 * ntp + 1], al[mt], bb[ntp][2], bb[ntp][3]);
                }
        }
        if (pf) STORE_B2((uint32_t)(((ck + 1) & 1) * STAGE_BYTES));
        __syncthreads();
    }
#undef LOAD_A2
#undef FETCH_B2
#undef STORE_B2

#pragma unroll
    for (int mt = 0; mt < 2; mt++) {
        int row = row0 + wm * 32 + mt * 16 + qr;
#pragma unroll
        for (int nt = 0; nt < 8; nt++) {
            int col = col0 + wn * 64 + nt * 8 + qc;
            float b0 = __ldg(&bias[col]);
            float b1 = __ldg(&bias[col + 1]);
            float2 o0 = make_float2(acc[mt][nt][0] + b0, acc[mt][nt][1] + b1);
            float2 o1 = make_float2(acc[mt][nt][2] + b0, acc[mt][nt][3] + b1);
            *(float2*)(C + (size_t)row * N + col) = o0;
            *(float2*)(C + (size_t)(row + 8) * N + col) = o1;
        }
    }
}

// ---------------------------------------------------------------------------
// depthwise conv3 + silu gate; emits y as fp16 hi/lo
// ---------------------------------------------------------------------------
__global__ __launch_bounds__(256)
void conv_gate_kernel(const float* __restrict__ Wc, const float* __restrict__ bc) {
    int idx = blockIdx.x * blockDim.x + threadIdx.x;
    int m = idx >> 8;
    int d = (idx & 255) << 2;
    int l = m & (LSEQ - 1);

    const float* urow = g_uv + (size_t)m * (2 * DDIM);
    const float* vrow = urow + DDIM;

    float4 vc = *(const float4*)(vrow + d);
    float4 vp = make_float4(0.f, 0.f, 0.f, 0.f);
    float4 vn = make_float4(0.f, 0.f, 0.f, 0.f);
    if (l > 0)        vp = *(const float4*)(vrow - 2 * DDIM + d);
    if (l < LSEQ - 1) vn = *(const float4*)(vrow + 2 * DDIM + d);
    float4 uu = *(const float4*)(urow + d);

    float p[4] = {vp.x, vp.y, vp.z, vp.w};
    float c[4] = {vc.x, vc.y, vc.z, vc.w};
    float n[4] = {vn.x, vn.y, vn.z, vn.w};
    float u[4] = {uu.x, uu.y, uu.z, uu.w};
    float o[4];
#pragma unroll
    for (int j = 0; j < 4; j++) {
        int dd = d + j;
        float t = fmaf(p[j], Wc[dd * 3 + 0],
                  fmaf(c[j], Wc[dd * 3 + 1],
                  fmaf(n[j], Wc[dd * 3 + 2], bc[dd])));
        float s = 1.f / (1.f + __expf(-t));
        o[j] = t * s * u[j];
    }
    __half2 H0 = __floats2half2_rn(o[0], o[1]);
    __half2 H1 = __floats2half2_rn(o[2], o[3]);
    __half2 L0 = __floats2half2_rn(o[0] - __low2float(H0), o[1] - __high2float(H0));
    __half2 L1 = __floats2half2_rn(o[2] - __low2float(H1), o[3] - __high2float(H1));
    size_t off = ((size_t)m * DDIM + d) * 2;
    *(uint2*)((char*)g_yhi + off) = make_uint2(*reinterpret_cast<uint32_t*>(&H0),
                                               *reinterpret_cast<uint32_t*>(&H1));
    *(uint2*)((char*)g_ylo + off) = make_uint2(*reinterpret_cast<uint32_t*>(&L0),
                                               *reinterpret_cast<uint32_t*>(&L1));
}

// ---------------------------------------------------------------------------
extern "C" void kernel_launch(void* const* d_in, const int* in_sizes, int n_in,
                              void* d_out, int out_size) {
    const float* x  = (const float*)d_in[0];
    const float* Wi = (const float*)d_in[1];
    const float* bi = (const float*)d_in[2];
    const float* Wc = (const float*)d_in[3];
    const float* bc = (const float*)d_in[4];
    const float* Wo = (const float*)d_in[5];
    const float* bo = (const float*)d_in[6];
    float* out = (float*)d_out;

    float* uv_ptr;
    __half *yhi, *ylo;
    cudaGetSymbolAddress((void**)&uv_ptr, g_uv);
    cudaGetSymbolAddress((void**)&yhi, g_yhi);
    cudaGetSymbolAddress((void**)&ylo, g_ylo);

    cudaFuncSetAttribute(gemm1_fused<2 * DDIM, DDIM>,
                         cudaFuncAttributeMaxDynamicSharedMemorySize, SMEMSZ);
    cudaFuncSetAttribute(gemm2_fused<DDIM, DDIM>,
                         cudaFuncAttributeMaxDynamicSharedMemorySize, SMEMSZ);

    {   // GEMM1: uv = x @ Wi^T + bi  (fp32 in, converted in loader)
        dim3 grid(2 * DDIM / BN, MROWS / BM);
        gemm1_fused<2 * DDIM, DDIM><<<grid, NTH, SMEMSZ>>>(x, Wi, bi, uv_ptr);
    }
    {   // conv + silu gate -> y hi/lo
        int total = MROWS * (DDIM / 4);
        conv_gate_kernel<<<total / 256, 256>>>(Wc, bc);
    }
    {   // GEMM2: out = y @ Wo^T + bo  (Wo converted in loader)
        dim3 grid(DDIM / BN, MROWS / BM);
        gemm2_fused<DDIM, DDIM><<<grid, NTH, SMEMSZ>>>(yhi, ylo, Wo, bo, out);
    }
}

// round 10
// speedup vs baseline: 1.1564x; 1.1564x over previous
#include <cuda_runtime.h>
#include <cuda_fp16.h>
#include <cstdint>

// ============================================================================
// MambaBlock, fp16 asymmetric 2-product HMMA (A = hi+lo fp16, B = fp16 round).
// R9: R7 architecture (standalone cvt kernels, all-fp16 cp.async GEMM) with a
// 3-stage cp.async ring and single-sync loop.
// ============================================================================

#define MROWS 16384
#define DDIM  1024
#define LSEQ  4096

#define BM 128
#define BN 128
#define BK 32
#define SP 40                    // SMEM row stride in fp16 (32 + 8 pad)
#define NTH 256

#define A_HI 0
#define A_LO (BM * SP * 2)       // 10240
#define B_OF (2 * BM * SP * 2)   // 20480
#define STAGE_BYTES (3 * BM * SP * 2)   // 30720
#define NSTAGE 3
#define SMEMSZ (NSTAGE * STAGE_BYTES)   // 92160

__device__ float g_uv[(size_t)MROWS * 2 * DDIM];
__device__ __half g_xhi[(size_t)MROWS * DDIM];
__device__ __half g_xlo[(size_t)MROWS * DDIM];
__device__ __half g_yhi[(size_t)MROWS * DDIM];
__device__ __half g_ylo[(size_t)MROWS * DDIM];
__device__ __half g_wi [(size_t)2 * DDIM * DDIM];
__device__ __half g_wo [(size_t)DDIM * DDIM];

__device__ __forceinline__ void mma_f16(float* c, const uint32_t* a,
                                        uint32_t b0, uint32_t b1) {
    asm volatile(
        "mma.sync.aligned.m16n8k16.row.col.f32.f16.f16.f32 "
        "{%0,%1,%2,%3}, {%4,%5,%6,%7}, {%8,%9}, {%0,%1,%2,%3};"
        : "+f"(c[0]), "+f"(c[1]), "+f"(c[2]), "+f"(c[3])
        : "r"(a[0]), "r"(a[1]), "r"(a[2]), "r"(a[3]), "r"(b0), "r"(b1));
}

#define LDSM4(r0, r1, r2, r3, addr)                                        \
    asm volatile("ldmatrix.sync.aligned.m8n8.x4.shared.b16 {%0,%1,%2,%3}, [%4];" \
                 : "=r"(r0), "=r"(r1), "=r"(r2), "=r"(r3) : "r"(addr))

#define CPA16(dst, src) \
    asm volatile("cp.async.cg.shared.global [%0], [%1], 16;" :: "r"(dst), "l"(src))
#define CP_COMMIT() asm volatile("cp.async.commit_group;" ::: "memory")
#define CP_WAIT1()  asm volatile("cp.async.wait_group 1;" ::: "memory")
#define CP_WAIT0()  asm volatile("cp.async.wait_group 0;" ::: "memory")

// fp32x4 -> fp16 hi (2 words) + fp16 lo residual (2 words)
__device__ __forceinline__ void cvt_hilo4(float4 v, uint32_t& h0, uint32_t& h1,
                                          uint32_t& l0, uint32_t& l1) {
    __half2 H0 = __floats2half2_rn(v.x, v.y);
    __half2 H1 = __floats2half2_rn(v.z, v.w);
    float r0 = v.x - __low2float(H0);
    float r1 = v.y - __high2float(H0);
    float r2 = v.z - __low2float(H1);
    float r3 = v.w - __high2float(H1);
    __half2 L0 = __floats2half2_rn(r0, r1);
    __half2 L1 = __floats2half2_rn(r2, r3);
    h0 = *reinterpret_cast<uint32_t*>(&H0);
    h1 = *reinterpret_cast<uint32_t*>(&H1);
    l0 = *reinterpret_cast<uint32_t*>(&L0);
    l1 = *reinterpret_cast<uint32_t*>(&L1);
}

__global__ __launch_bounds__(256)
void cvt_split_kernel(const float* __restrict__ src, __half* __restrict__ hi,
                      __half* __restrict__ lo) {
    size_t i4 = ((size_t)blockIdx.x * 256 + threadIdx.x) * 4;
    float4 v = *(const float4*)(src + i4);
    uint32_t h0, h1, l0, l1;
    cvt_hilo4(v, h0, h1, l0, l1);
    *(uint2*)((char*)hi + i4 * 2) = make_uint2(h0, h1);
    *(uint2*)((char*)lo + i4 * 2) = make_uint2(l0, l1);
}

__global__ __launch_bounds__(256)
void cvt_round_kernel(const float* __restrict__ src, __half* __restrict__ dst) {
    size_t i4 = ((size_t)blockIdx.x * 256 + threadIdx.x) * 4;
    float4 v = *(const float4*)(src + i4);
    __half2 H0 = __floats2half2_rn(v.x, v.y);
    __half2 H1 = __floats2half2_rn(v.z, v.w);
    *(uint2*)((char*)dst + i4 * 2) =
        make_uint2(*reinterpret_cast<uint32_t*>(&H0), *reinterpret_cast<uint32_t*>(&H1));
}

// ---------------------------------------------------------------------------
// C[M,N] = (Ahi+Alo)[M,K] @ B[N,K]^T + bias
// ---------------------------------------------------------------------------
template <int N, int K>
__global__ __launch_bounds__(NTH, 2)
void gemm_mma(const __half* __restrict__ Ahi, const __half* __restrict__ Alo,
              const __half* __restrict__ B,
              const float* __restrict__ bias, float* __restrict__ C) {
    extern __shared__ __align__(16) char sm[];
    const uint32_t smb = (uint32_t)__cvta_generic_to_shared(sm);
    const int tid  = threadIdx.x;
    const int lane = tid & 31;
    const int wid  = tid >> 5;
    const int wm   = wid & 3;
    const int wn   = wid >> 2;
    const int qr   = lane >> 2;
    const int qc   = (lane & 3) * 2;
    const int row0 = blockIdx.y * BM;
    const int col0 = blockIdx.x * BN;

    const int m8 = lane >> 3;
    const int rr = lane & 7;
    const uint32_t aLane = (uint32_t)(((wm * 32 + (m8 & 1) * 8 + rr) * SP + (m8 >> 1) * 8) * 2);
    const uint32_t bLane = (uint32_t)(((wn * 64 + (m8 >> 1) * 8 + rr) * SP + (m8 & 1) * 8) * 2);

    const int l_r0 = tid >> 2;       // rows 0..63, +64
    const int l_c  = (tid & 3) * 16;

    float acc[2][8][4];
#pragma unroll
    for (int i = 0; i < 2; i++)
#pragma unroll
        for (int j = 0; j < 8; j++)
#pragma unroll
            for (int k = 0; k < 4; k++) acc[i][j][k] = 0.f;

    const char* pAh = (const char*)(Ahi + (size_t)row0 * K);
    const char* pAl = (const char*)(Alo + (size_t)row0 * K);
    const char* pB  = (const char*)(B   + (size_t)col0 * K);

#define LOAD_STAGE(stageOff, kt) do {                                          \
    const uint32_t so_ = smb + (stageOff);                                     \
    const size_t kb_ = (size_t)(kt) * 2;                                       \
    _Pragma("unroll")                                                          \
    for (int rep = 0; rep < 2; rep++) {                                        \
        int r = l_r0 + rep * 64;                                               \
        uint32_t d = so_ + (uint32_t)(r * (SP * 2) + l_c);                     \
        size_t g = (size_t)r * (K * 2) + kb_ + l_c;                            \
        CPA16(d + A_HI, pAh + g);                                              \
        CPA16(d + A_LO, pAl + g);                                              \
        CPA16(d + B_OF, pB  + g);                                              \
    }                                                                          \
} while (0)

    // prologue: stages 0 and 1
    LOAD_STAGE(0, 0);
    CP_COMMIT();
    LOAD_STAGE(STAGE_BYTES, BK);
    CP_COMMIT();

    constexpr int NCH = K / BK;
    int s_cur = 0, s_nxt = 2;        // stage (ck % 3), stage ((ck+2) % 3)
#pragma unroll 1
    for (int ck = 0; ck < NCH; ck++) {
        if (ck + 1 < NCH) CP_WAIT1(); else CP_WAIT0();
        __syncthreads();             // seals compute of ck-1 -> stage s_nxt reusable
        if (ck + 2 < NCH) {
            LOAD_STAGE((uint32_t)(s_nxt * STAGE_BYTES), (ck + 2) * BK);
            CP_COMMIT();
        }

        const uint32_t sto = smb + (uint32_t)(s_cur * STAGE_BYTES);
#pragma unroll
        for (int kb = 0; kb < BK; kb += 16) {
            uint32_t ah[2][4], al[2][4], bb[4][4];
#pragma unroll
            for (int mt = 0; mt < 2; mt++) {
                uint32_t ao = sto + aLane + (uint32_t)((mt * 16 * SP + kb) * 2);
                LDSM4(ah[mt][0], ah[mt][1], ah[mt][2], ah[mt][3], ao + A_HI);
                LDSM4(al[mt][0], al[mt][1], al[mt][2], al[mt][3], ao + A_LO);
            }
#pragma unroll
            for (int ntp = 0; ntp < 4; ntp++) {
                uint32_t bo = sto + bLane + (uint32_t)((ntp * 16 * SP + kb) * 2);
                LDSM4(bb[ntp][0], bb[ntp][1], bb[ntp][2], bb[ntp][3], bo + B_OF);
            }
            // pass 1: Ahi * B (16 independent accumulators)
#pragma unroll
            for (int mt = 0; mt < 2; mt++)
#pragma unroll
                for (int ntp = 0; ntp < 4; ntp++) {
                    mma_f16(acc[mt][2 * ntp],     ah[mt], bb[ntp][0], bb[ntp][1]);
                    mma_f16(acc[mt][2 * ntp + 1], ah[mt], bb[ntp][2], bb[ntp][3]);
                }
            // pass 2: Alo * B
#pragma unroll
            for (int mt = 0; mt < 2; mt++)
#pragma unroll
                for (int ntp = 0; ntp < 4; ntp++) {
                    mma_f16(acc[mt][2 * ntp],     al[mt], bb[ntp][0], bb[ntp][1]);
                    mma_f16(acc[mt][2 * ntp + 1], al[mt], bb[ntp][2], bb[ntp][3]);
                }
        }
        s_cur = (s_cur == 2) ? 0 : s_cur + 1;
        s_nxt = (s_nxt == 2) ? 0 : s_nxt + 1;
    }
#undef LOAD_STAGE

    // epilogue: bias + store
#pragma unroll
    for (int mt = 0; mt < 2; mt++) {
        int row = row0 + wm * 32 + mt * 16 + qr;
#pragma unroll
        for (int nt = 0; nt < 8; nt++) {
            int col = col0 + wn * 64 + nt * 8 + qc;
            float b0 = __ldg(&bias[col]);
            float b1 = __ldg(&bias[col + 1]);
            float2 o0 = make_float2(acc[mt][nt][0] + b0, acc[mt][nt][1] + b1);
            float2 o1 = make_float2(acc[mt][nt][2] + b0, acc[mt][nt][3] + b1);
            *(float2*)(C + (size_t)row * N + col) = o0;
            *(float2*)(C + (size_t)(row + 8) * N + col) = o1;
        }
    }
}

// ---------------------------------------------------------------------------
// depthwise conv3 + silu gate; emits y as fp16 hi/lo
// ---------------------------------------------------------------------------
__global__ __launch_bounds__(256)
void conv_gate_kernel(const float* __restrict__ Wc, const float* __restrict__ bc) {
    int idx = blockIdx.x * blockDim.x + threadIdx.x;
    int m = idx >> 8;
    int d = (idx & 255) << 2;
    int l = m & (LSEQ - 1);

    const float* urow = g_uv + (size_t)m * (2 * DDIM);
    const float* vrow = urow + DDIM;

    float4 vc = *(const float4*)(vrow + d);
    float4 vp = make_float4(0.f, 0.f, 0.f, 0.f);
    float4 vn = make_float4(0.f, 0.f, 0.f, 0.f);
    if (l > 0)        vp = *(const float4*)(vrow - 2 * DDIM + d);
    if (l < LSEQ - 1) vn = *(const float4*)(vrow + 2 * DDIM + d);
    float4 uu = *(const float4*)(urow + d);

    float p[4] = {vp.x, vp.y, vp.z, vp.w};
    float c[4] = {vc.x, vc.y, vc.z, vc.w};
    float n[4] = {vn.x, vn.y, vn.z, vn.w};
    float u[4] = {uu.x, uu.y, uu.z, uu.w};
    float o[4];
#pragma unroll
    for (int j = 0; j < 4; j++) {
        int dd = d + j;
        float t = fmaf(p[j], Wc[dd * 3 + 0],
                  fmaf(c[j], Wc[dd * 3 + 1],
                  fmaf(n[j], Wc[dd * 3 + 2], bc[dd])));
        float s = 1.f / (1.f + __expf(-t));
        o[j] = t * s * u[j];
    }
    uint32_t h0, h1, l0, l1;
    cvt_hilo4(make_float4(o[0], o[1], o[2], o[3]), h0, h1, l0, l1);
    size_t off = ((size_t)m * DDIM + d) * 2;
    *(uint2*)((char*)g_yhi + off) = make_uint2(h0, h1);
    *(uint2*)((char*)g_ylo + off) = make_uint2(l0, l1);
}

// ---------------------------------------------------------------------------
extern "C" void kernel_launch(void* const* d_in, const int* in_sizes, int n_in,
                              void* d_out, int out_size) {
    const float* x  = (const float*)d_in[0];
    const float* Wi = (const float*)d_in[1];
    const float* bi = (const float*)d_in[2];
    const float* Wc = (const float*)d_in[3];
    const float* bc = (const float*)d_in[4];
    const float* Wo = (const float*)d_in[5];
    const float* bo = (const float*)d_in[6];
    float* out = (float*)d_out;

    float* uv_ptr;
    __half *xhi, *xlo, *yhi, *ylo, *wi, *wo;
    cudaGetSymbolAddress((void**)&uv_ptr, g_uv);
    cudaGetSymbolAddress((void**)&xhi, g_xhi);
    cudaGetSymbolAddress((void**)&xlo, g_xlo);
    cudaGetSymbolAddress((void**)&yhi, g_yhi);
    cudaGetSymbolAddress((void**)&ylo, g_ylo);
    cudaGetSymbolAddress((void**)&wi,  g_wi);
    cudaGetSymbolAddress((void**)&wo,  g_wo);

    cudaFuncSetAttribute(gemm_mma<2 * DDIM, DDIM>,
                         cudaFuncAttributeMaxDynamicSharedMemorySize, SMEMSZ);
    cudaFuncSetAttribute(gemm_mma<DDIM, DDIM>,
                         cudaFuncAttributeMaxDynamicSharedMemorySize, SMEMSZ);

    // pre-convert: x -> fp16 hi/lo split; Wi, Wo -> fp16 round
    cvt_split_kernel<<<(MROWS * DDIM) / 1024, 256>>>(x, xhi, xlo);
    cvt_round_kernel<<<(2 * DDIM * DDIM) / 1024, 256>>>(Wi, wi);
    cvt_round_kernel<<<(DDIM * DDIM) / 1024, 256>>>(Wo, wo);

    {   // GEMM1: uv = x @ Wi^T + bi
        dim3 grid(2 * DDIM / BN, MROWS / BM);
        gemm_mma<2 * DDIM, DDIM><<<grid, NTH, SMEMSZ>>>(xhi, xlo, wi, bi, uv_ptr);
    }
    {   // conv + silu gate -> y hi/lo
        int total = MROWS * (DDIM / 4);
        conv_gate_kernel<<<total / 256, 256>>>(Wc, bc);
    }
    {   // GEMM2: out = y @ Wo^T + bo
        dim3 grid(DDIM / BN, MROWS / BM);
        gemm_mma<DDIM, DDIM><<<grid, NTH, SMEMSZ>>>(yhi, ylo, wo, bo, out);
    }
}

// round 12
// speedup vs baseline: 1.7884x; 1.5465x over previous
#include <cuda_runtime.h>
#include <cuda_fp16.h>
#include <cstdint>

// ============================================================================
// MambaBlock, single-product fp16 HMMA (A and B both fp16-rounded, fp32 acc).
//   uv = x@Wi^T+bi ; y = silu(dwconv3(v))*u ; out = y@Wo^T+bo
// Error model: fp16 rounding on both operands -> rel_err ~ 4e-4 (< 1e-3).
// 3-stage cp.async ring, 128x128x32 tile, 8 warps, 2 CTAs/SM.
// ============================================================================

#define MROWS 16384
#define DDIM  1024
#define LSEQ  4096

#define BM 128
#define BN 128
#define BK 32
#define SP 40                    // SMEM row stride in fp16 (32 + 8 pad)
#define NTH 256

#define A_OF 0
#define B_OF (BM * SP * 2)       // 10240
#define STAGE_BYTES (2 * BM * SP * 2)   // 20480
#define NSTAGE 3
#define SMEMSZ (NSTAGE * STAGE_BYTES)   // 61440

__device__ float g_uv[(size_t)MROWS * 2 * DDIM];
__device__ __half g_xh[(size_t)MROWS * DDIM];
__device__ __half g_yh[(size_t)MROWS * DDIM];
__device__ __half g_wi[(size_t)2 * DDIM * DDIM];
__device__ __half g_wo[(size_t)DDIM * DDIM];

__device__ __forceinline__ void mma_f16(float* c, const uint32_t* a,
                                        uint32_t b0, uint32_t b1) {
    asm volatile(
        "mma.sync.aligned.m16n8k16.row.col.f32.f16.f16.f32 "
        "{%0,%1,%2,%3}, {%4,%5,%6,%7}, {%8,%9}, {%0,%1,%2,%3};"
        : "+f"(c[0]), "+f"(c[1]), "+f"(c[2]), "+f"(c[3])
        : "r"(a[0]), "r"(a[1]), "r"(a[2]), "r"(a[3]), "r"(b0), "r"(b1));
}

#define LDSM4(r0, r1, r2, r3, addr)                                        \
    asm volatile("ldmatrix.sync.aligned.m8n8.x4.shared.b16 {%0,%1,%2,%3}, [%4];" \
                 : "=r"(r0), "=r"(r1), "=r"(r2), "=r"(r3) : "r"(addr))

#define CPA16(dst, src) \
    asm volatile("cp.async.cg.shared.global [%0], [%1], 16;" :: "r"(dst), "l"(src))
#define CP_COMMIT() asm volatile("cp.async.commit_group;" ::: "memory")
#define CP_WAIT1()  asm volatile("cp.async.wait_group 1;" ::: "memory")
#define CP_WAIT0()  asm volatile("cp.async.wait_group 0;" ::: "memory")

// round fp32x4 -> 2 fp16x2 words
__global__ __launch_bounds__(256)
void cvt_round_kernel(const float* __restrict__ src, __half* __restrict__ dst) {
    size_t i4 = ((size_t)blockIdx.x * 256 + threadIdx.x) * 4;
    float4 v = *(const float4*)(src + i4);
    __half2 H0 = __floats2half2_rn(v.x, v.y);
    __half2 H1 = __floats2half2_rn(v.z, v.w);
    *(uint2*)((char*)dst + i4 * 2) =
        make_uint2(*reinterpret_cast<uint32_t*>(&H0), *reinterpret_cast<uint32_t*>(&H1));
}

// ---------------------------------------------------------------------------
// C[M,N] = A[M,K] @ B[N,K]^T + bias   (fp16 operands, fp32 accumulate)
// ---------------------------------------------------------------------------
template <int N, int K>
__global__ __launch_bounds__(NTH, 2)
void gemm_mma(const __half* __restrict__ A, const __half* __restrict__ B,
              const float* __restrict__ bias, float* __restrict__ C) {
    extern __shared__ __align__(16) char sm[];
    const uint32_t smb = (uint32_t)__cvta_generic_to_shared(sm);
    const int tid  = threadIdx.x;
    const int lane = tid & 31;
    const int wid  = tid >> 5;
    const int wm   = wid & 3;
    const int wn   = wid >> 2;
    const int qr   = lane >> 2;
    const int qc   = (lane & 3) * 2;
    const int row0 = blockIdx.y * BM;
    const int col0 = blockIdx.x * BN;

    const int m8 = lane >> 3;
    const int rr = lane & 7;
    const uint32_t aLane = (uint32_t)(((wm * 32 + (m8 & 1) * 8 + rr) * SP + (m8 >> 1) * 8) * 2);
    const uint32_t bLane = (uint32_t)(((wn * 64 + (m8 >> 1) * 8 + rr) * SP + (m8 & 1) * 8) * 2);

    const int l_r0 = tid >> 2;       // rows 0..63, +64
    const int l_c  = (tid & 3) * 16;

    float acc[2][8][4];
#pragma unroll
    for (int i = 0; i < 2; i++)
#pragma unroll
        for (int j = 0; j < 8; j++)
#pragma unroll
            for (int k = 0; k < 4; k++) acc[i][j][k] = 0.f;

    const char* pA = (const char*)(A + (size_t)row0 * K);
    const char* pB = (const char*)(B + (size_t)col0 * K);

#define LOAD_STAGE(stageOff, kt) do {                                          \
    const uint32_t so_ = smb + (stageOff);                                     \
    const size_t kb_ = (size_t)(kt) * 2;                                       \
    _Pragma("unroll")                                                          \
    for (int rep = 0; rep < 2; rep++) {                                        \
        int r = l_r0 + rep * 64;                                               \
        uint32_t d = so_ + (uint32_t)(r * (SP * 2) + l_c);                     \
        size_t g = (size_t)r * (K * 2) + kb_ + l_c;                            \
        CPA16(d + A_OF, pA + g);                                               \
        CPA16(d + B_OF, pB + g);                                               \
    }                                                                          \
} while (0)

    // prologue: stages 0, 1
    LOAD_STAGE(0, 0);
    CP_COMMIT();
    LOAD_STAGE(STAGE_BYTES, BK);
    CP_COMMIT();

    constexpr int NCH = K / BK;
    int s_cur = 0, s_nxt = 2;
#pragma unroll 1
    for (int ck = 0; ck < NCH; ck++) {
        if (ck + 1 < NCH) CP_WAIT1(); else CP_WAIT0();
        __syncthreads();
        if (ck + 2 < NCH) {
            LOAD_STAGE((uint32_t)(s_nxt * STAGE_BYTES), (ck + 2) * BK);
            CP_COMMIT();
        }

        const uint32_t sto = smb + (uint32_t)(s_cur * STAGE_BYTES);
#pragma unroll
        for (int kb = 0; kb < BK; kb += 16) {
            uint32_t aa[2][4], bb[4][4];
#pragma unroll
            for (int mt = 0; mt < 2; mt++) {
                uint32_t ao = sto + aLane + (uint32_t)((mt * 16 * SP + kb) * 2);
                LDSM4(aa[mt][0], aa[mt][1], aa[mt][2], aa[mt][3], ao + A_OF);
            }
#pragma unroll
            for (int ntp = 0; ntp < 4; ntp++) {
                uint32_t bo = sto + bLane + (uint32_t)((ntp * 16 * SP + kb) * 2);
                LDSM4(bb[ntp][0], bb[ntp][1], bb[ntp][2], bb[ntp][3], bo + B_OF);
            }
#pragma unroll
            for (int mt = 0; mt < 2; mt++)
#pragma unroll
                for (int ntp = 0; ntp < 4; ntp++) {
                    mma_f16(acc[mt][2 * ntp],     aa[mt], bb[ntp][0], bb[ntp][1]);
                    mma_f16(acc[mt][2 * ntp + 1], aa[mt], bb[ntp][2], bb[ntp][3]);
                }
        }
        s_cur = (s_cur == 2) ? 0 : s_cur + 1;
        s_nxt = (s_nxt == 2) ? 0 : s_nxt + 1;
    }
#undef LOAD_STAGE

    // epilogue: bias + store
#pragma unroll
    for (int mt = 0; mt < 2; mt++) {
        int row = row0 + wm * 32 + mt * 16 + qr;
#pragma unroll
        for (int nt = 0; nt < 8; nt++) {
            int col = col0 + wn * 64 + nt * 8 + qc;
            float b0 = __ldg(&bias[col]);
            float b1 = __ldg(&bias[col + 1]);
            float2 o0 = make_float2(acc[mt][nt][0] + b0, acc[mt][nt][1] + b1);
            float2 o1 = make_float2(acc[mt][nt][2] + b0, acc[mt][nt][3] + b1);
            *(float2*)(C + (size_t)row * N + col) = o0;
            *(float2*)(C + (size_t)(row + 8) * N + col) = o1;
        }
    }
}

// ---------------------------------------------------------------------------
// depthwise conv3 + silu gate; emits y as fp16
// ---------------------------------------------------------------------------
__global__ __launch_bounds__(256)
void conv_gate_kernel(const float* __restrict__ Wc, const float* __restrict__ bc) {
    int idx = blockIdx.x * blockDim.x + threadIdx.x;
    int m = idx >> 8;
    int d = (idx & 255) << 2;
    int l = m & (LSEQ - 1);

    const float* urow = g_uv + (size_t)m * (2 * DDIM);
    const float* vrow = urow + DDIM;

    float4 vc = *(const float4*)(vrow + d);
    float4 vp = make_float4(0.f, 0.f, 0.f, 0.f);
    float4 vn = make_float4(0.f, 0.f, 0.f, 0.f);
    if (l > 0)        vp = *(const float4*)(vrow - 2 * DDIM + d);
    if (l < LSEQ - 1) vn = *(const float4*)(vrow + 2 * DDIM + d);
    float4 uu = *(const float4*)(urow + d);

    float p[4] = {vp.x, vp.y, vp.z, vp.w};
    float c[4] = {vc.x, vc.y, vc.z, vc.w};
    float n[4] = {vn.x, vn.y, vn.z, vn.w};
    float u[4] = {uu.x, uu.y, uu.z, uu.w};
    float o[4];
#pragma unroll
    for (int j = 0; j < 4; j++) {
        int dd = d + j;
        float t = fmaf(p[j], Wc[dd * 3 + 0],
                  fmaf(c[j], Wc[dd * 3 + 1],
                  fmaf(n[j], Wc[dd * 3 + 2], bc[dd])));
        float s = 1.f / (1.f + __expf(-t));
        o[j] = t * s * u[j];
    }
    __half2 H0 = __floats2half2_rn(o[0], o[1]);
    __half2 H1 = __floats2half2_rn(o[2], o[3]);
    size_t off = ((size_t)m * DDIM + d) * 2;
    *(uint2*)((char*)g_yh + off) = make_uint2(*reinterpret_cast<uint32_t*>(&H0),
                                              *reinterpret_cast<uint32_t*>(&H1));
}

// ---------------------------------------------------------------------------
extern "C" void kernel_launch(void* const* d_in, const int* in_sizes, int n_in,
                              void* d_out, int out_size) {
    const float* x  = (const float*)d_in[0];
    const float* Wi = (const float*)d_in[1];
    const float* bi = (const float*)d_in[2];
    const float* Wc = (const float*)d_in[3];
    const float* bc = (const float*)d_in[4];
    const float* Wo = (const float*)d_in[5];
    const float* bo = (const float*)d_in[6];
    float* out = (float*)d_out;

    float* uv_ptr;
    __half *xh, *yh, *wi, *wo;
    cudaGetSymbolAddress((void**)&uv_ptr, g_uv);
    cudaGetSymbolAddress((void**)&xh, g_xh);
    cudaGetSymbolAddress((void**)&yh, g_yh);
    cudaGetSymbolAddress((void**)&wi, g_wi);
    cudaGetSymbolAddress((void**)&wo, g_wo);

    cudaFuncSetAttribute(gemm_mma<2 * DDIM, DDIM>,
                         cudaFuncAttributeMaxDynamicSharedMemorySize, SMEMSZ);
    cudaFuncSetAttribute(gemm_mma<DDIM, DDIM>,
                         cudaFuncAttributeMaxDynamicSharedMemorySize, SMEMSZ);

    // round x, Wi, Wo to fp16
    cvt_round_kernel<<<(MROWS * DDIM) / 1024, 256>>>(x, xh);
    cvt_round_kernel<<<(2 * DDIM * DDIM) / 1024, 256>>>(Wi, wi);
    cvt_round_kernel<<<(DDIM * DDIM) / 1024, 256>>>(Wo, wo);

    {   // GEMM1: uv = x @ Wi^T + bi
        dim3 grid(2 * DDIM / BN, MROWS / BM);
        gemm_mma<2 * DDIM, DDIM><<<grid, NTH, SMEMSZ>>>(xh, wi, bi, uv_ptr);
    }
    {   // conv + silu gate -> y fp16
        int total = MROWS * (DDIM / 4);
        conv_gate_kernel<<<total / 256, 256>>>(Wc, bc);
    }
    {   // GEMM2: out = y @ Wo^T + bo
        dim3 grid(DDIM / BN, MROWS / BM);
        gemm_mma<DDIM, DDIM><<<grid, NTH, SMEMSZ>>>(yh, wo, bo, out);
    }
}